// round 15
// baseline (speedup 1.0000x reference)
#include <cuda_runtime.h>
#include <cuda_fp16.h>
#include <cstdint>

// ---------------------------------------------------------------------------
// FanoCoupling: persistent HMMA, warp-specialized producer/consumer pipeline.
//
//   W = [W1|W2]; A0=W1x0 A1=W1x1 A3=W1x3 A4=W1x4 B1=W2x1 B2=W2x2 B3=W2x3 B5=W2x5
//   out0=x0 out1=x1 out3=x3
//   out2 = x2 + g0*(A0+B1+b)
//   out4 = x4 + g1*(A0+B3+b)
//   out5 = x5 + g3*(A1+B3+b) + g6*(A4+B2+b)
//   out6 = x6 + g2*(A0+B5+b) + g4*(A4+B1+b) + g5*(A3+B2+b)
//
// Warps 4-7 (producers): cp.async fp32 tile -> producer-group barrier (the
// R13 race fix: cp.async wait-groups are PER-THREAD; all producers must
// rendezvous before any thread reads the tile) -> fp32->fp16 convert ->
// FULL arrive -> pass-through stores.  Warps 0-3 (consumers): FULL sync ->
// ldmatrix + mma.sync m16n8k16 -> residual epilogue -> FREE arrive.
// 2-stage buf/xh; named barriers: FULL_s=1+s, FREE_s=3+s (256), PROD=5 (128).
// 2 CTAs/SM.  Consumer warp = 16 rows x 16 z.
// ---------------------------------------------------------------------------

#define ROW 448
#define TROWS 16
#define BSTR 452                        // floats per buffered row (16B pad)
#define BUF_FLOATS (TROWS * BSTR)       // 7232
#define STR 72                          // halves per fp16 row
#define XH_COLONY (TROWS * STR)         // 1152
#define XH_STAGE (6 * XH_COLONY)        // 6912 halves per stage
#define WH_HALF (64 * STR)              // 4608
#define SMEM_BYTES (2 * BUF_FLOATS * 4 + (2 * XH_STAGE + 2 * WH_HALF) * 2) // 103936
#define NTHR 256

#define BAR_SYNC(id)   asm volatile("bar.sync %0, 256;"   :: "r"(id) : "memory")
#define BAR_ARRIVE(id) asm volatile("bar.arrive %0, 256;" :: "r"(id) : "memory")
#define BAR_PROD()     asm volatile("bar.sync 5, 128;" ::: "memory")

__device__ __half whg[8192];            // [h][z][f] fp16 weights

__global__ void pack_w(const float* __restrict__ W) {
    int i = blockIdx.x * 256 + threadIdx.x;
    if (i < 8192) {
        int z = i >> 7, f = i & 127;
        whg[(f >> 6) * 4096 + z * 64 + (f & 63)] = __float2half_rn(W[i]);
    }
}

__device__ __forceinline__ uint32_t s2u(const void* p) {
    uint32_t a;
    asm("{ .reg .u64 t; cvta.to.shared.u64 t, %1; cvt.u32.u64 %0, t; }" : "=r"(a) : "l"(p));
    return a;
}
__device__ __forceinline__ void cpasync16(uint32_t dst, const void* src) {
    asm volatile("cp.async.cg.shared.global [%0], [%1], 16;" :: "r"(dst), "l"(src));
}
#define CP_COMMIT() asm volatile("cp.async.commit_group;" ::: "memory")
#define CP_WAIT1()  asm volatile("cp.async.wait_group 1;" ::: "memory")
#define CP_WAIT0()  asm volatile("cp.async.wait_group 0;" ::: "memory")

__device__ __forceinline__ void ldm4(uint32_t* r, uint32_t addr) {
    asm volatile("ldmatrix.sync.aligned.m8n8.x4.shared.b16 {%0,%1,%2,%3}, [%4];"
                 : "=r"(r[0]), "=r"(r[1]), "=r"(r[2]), "=r"(r[3]) : "r"(addr));
}
__device__ __forceinline__ void mma16816(float* d, const uint32_t* a, const uint32_t* b) {
    asm volatile("mma.sync.aligned.m16n8k16.row.col.f32.f16.f16.f32 "
                 "{%0,%1,%2,%3}, {%4,%5,%6,%7}, {%8,%9}, {%0,%1,%2,%3};"
                 : "+f"(d[0]), "+f"(d[1]), "+f"(d[2]), "+f"(d[3])
                 : "r"(a[0]), "r"(a[1]), "r"(a[2]), "r"(a[3]), "r"(b[0]), "r"(b[1]));
}

__global__ __launch_bounds__(NTHR, 2)
void fano_mma(const float* __restrict__ x, const float* __restrict__ bias,
              const float* __restrict__ gates, float* __restrict__ out, int nrows)
{
    extern __shared__ float smf[];
    float*  bufs[2] = { smf, smf + BUF_FLOATS };
    __half* xh = reinterpret_cast<__half*>(smf + 2 * BUF_FLOATS);   // 2 stages
    __half* wh = xh + 2 * XH_STAGE;

    const int tid = threadIdx.x;
    const int G = gridDim.x;
    const int NT = (nrows + TROWS - 1) / TROWS;
    const int bid = blockIdx.x;
    const int K = (bid < NT) ? (NT - bid + G - 1) / G : 0;

    // --- stage fp16 W once (all threads) ------------------------------------
    {
        const uint4* wg = reinterpret_cast<const uint4*>(whg);
        for (int i = tid; i < 1024; i += NTHR) {
            int hz = i >> 3, f8 = (i & 7) * 8;
            *reinterpret_cast<uint4*>(wh + hz * STR + f8) = wg[i];
        }
    }
    __syncthreads();

    const int warp = tid >> 5, lane = tid & 31;
    const uint32_t bufu[2] = { s2u(bufs[0]), s2u(bufs[1]) };

    if (warp >= 4) {
        // =================== PRODUCER (warps 4-7) ===========================
        const int ptid = tid - 128;

        // prologue: load tile 0 into buf[0]
        if (K > 0) {
            const long long t0 = bid;
            const float* src = x + t0 * TROWS * ROW;
            long long rowb = t0 * (long long)TROWS;
            int r = ptid / 112, ch = ptid % 112;
            #pragma unroll
            for (int j = 0; j < 14; j++) {
                if (rowb + r < nrows)
                    cpasync16(bufu[0] + (uint32_t)(r * BSTR + ch * 4) * 4,
                              src + r * ROW + ch * 4);
                ch += 16; r += 1; if (ch >= 112) { ch -= 112; r += 1; }
            }
        }
        CP_COMMIT();

        for (int k = 0; k < K; k++) {
            const int s = k & 1;
            const long long t = bid + (long long)k * G;
            const long long rowb = t * TROWS;

            if (k >= 1) BAR_SYNC(3 + (s ^ 1));        // FREE_{s^1}: consumers done t_{k-1}

            // issue load of tile k+1 into the other stage
            if (k + 1 < K) {
                const long long tn = bid + (long long)(k + 1) * G;
                const float* src = x + tn * TROWS * ROW;
                long long rowbn = tn * TROWS;
                int r = ptid / 112, ch = ptid % 112;
                #pragma unroll
                for (int j = 0; j < 14; j++) {
                    if (rowbn + r < nrows)
                        cpasync16(bufu[s ^ 1] + (uint32_t)(r * BSTR + ch * 4) * 4,
                                  src + r * ROW + ch * 4);
                    ch += 16; r += 1; if (ch >= 112) { ch -= 112; r += 1; }
                }
                CP_COMMIT();
                CP_WAIT1();                           // this thread's tile-k copies done
            } else {
                CP_COMMIT();
                CP_WAIT0();
            }
            BAR_PROD();     // RACE FIX: ALL producers' tile-k copies visible

            const float* buf = bufs[s];
            __half* xs = xh + s * XH_STAGE;

            // convert colonies 0..5 fp32 -> fp16 (12 chunks/thread)
            {
                int r = ptid / 96, rem = ptid % 96;
                #pragma unroll
                for (int j = 0; j < 12; j++) {
                    int c = rem >> 4, f4 = (rem & 15) * 4;
                    float4 v = *reinterpret_cast<const float4*>(buf + r * BSTR + c * 64 + f4);
                    __half2 h01 = __floats2half2_rn(v.x, v.y);
                    __half2 h23 = __floats2half2_rn(v.z, v.w);
                    *reinterpret_cast<uint2*>(xs + c * XH_COLONY + r * STR + f4) =
                        make_uint2(*reinterpret_cast<uint32_t*>(&h01),
                                   *reinterpret_cast<uint32_t*>(&h23));
                    rem += 32; r += 1; if (rem >= 96) { rem -= 96; r += 1; }
                }
            }
            BAR_ARRIVE(1 + s);                        // FULL_s

            // pass-through colonies 0,1,3 (6 chunks/thread) — overlaps consumer
            {
                int r = ptid / 48, rem = ptid % 48;
                #pragma unroll
                for (int j = 0; j < 6; j++) {
                    int ci = rem / 16, f4 = (rem & 15) * 4;
                    int c = (ci < 2) ? ci : 3;
                    long long row = rowb + r;
                    if (row < nrows)
                        *reinterpret_cast<float4*>(out + row * (long long)ROW + c * 64 + f4) =
                            *reinterpret_cast<const float4*>(buf + r * BSTR + c * 64 + f4);
                    rem += 32; r += 2; if (rem >= 48) { rem -= 48; r += 1; }
                }
            }
        }
    } else {
        // =================== CONSUMER (warps 0-3) ===========================
        const int zbase = warp * 16;
        const int qrow = lane >> 2, qcol = (lane & 3) * 2;

        float g[7];
        {
            float graw[7];
            #pragma unroll
            for (int i = 0; i < 7; i++) graw[i] = gates[i];
            float m = graw[0];
            #pragma unroll
            for (int i = 1; i < 7; i++) m = fmaxf(m, graw[i]);
            float s = 0.f;
            #pragma unroll
            for (int i = 0; i < 7; i++) { g[i] = expf(graw[i] - m); s += g[i]; }
            float inv = 1.f / s;
            #pragma unroll
            for (int i = 0; i < 7; i++) g[i] *= inv;
        }
        float bz[2][2];
        #pragma unroll
        for (int nt = 0; nt < 2; nt++) {
            bz[nt][0] = bias[zbase + nt * 8 + qcol];
            bz[nt][1] = bias[zbase + nt * 8 + qcol + 1];
        }

        const int agrp = lane >> 3, alr = lane & 7;
        const int arow = alr + ((agrp & 1) ? 8 : 0);
        const int akk  = (agrp & 2) ? 8 : 0;
        const uint32_t aoff0 = s2u(xh) + (uint32_t)(arow * STR + akk) * 2;
        const int bz8 = (agrp & 2) ? 8 : 0;
        const int bkk = (agrp & 1) ? 8 : 0;
        const uint32_t boff = s2u(wh) + (uint32_t)((zbase + bz8 + alr) * STR + bkk) * 2;

        for (int k = 0; k < K; k++) {
            const int s = k & 1;
            const long long t = bid + (long long)k * G;
            const long long rowb = t * TROWS;
            const float* buf = bufs[s];
            const uint32_t aoff = aoff0 + (uint32_t)(s * XH_STAGE) * 2;

            BAR_SYNC(1 + s);                          // FULL_s: xh[s], buf[s] ready

            float acc[8][2][4];
            #pragma unroll
            for (int j = 0; j < 8; j++)
                #pragma unroll
                for (int nt = 0; nt < 2; nt++)
                    #pragma unroll
                    for (int q = 0; q < 4; q++) acc[j][nt][q] = 0.f;

            #pragma unroll
            for (int ks = 0; ks < 4; ks++) {
                const uint32_t k0b = (uint32_t)(ks * 16) * 2;
                uint32_t a[6][4];
                #pragma unroll
                for (int c = 0; c < 6; c++)
                    ldm4(a[c], aoff + (uint32_t)(c * XH_COLONY) * 2 + k0b);
                uint32_t b1[4], b2[4];
                ldm4(b1, boff + k0b);
                ldm4(b2, boff + (uint32_t)(WH_HALF) * 2 + k0b);
                #pragma unroll
                for (int nt = 0; nt < 2; nt++) {
                    mma16816(acc[0][nt], a[0], b1 + nt * 2);   // A0
                    mma16816(acc[1][nt], a[1], b1 + nt * 2);   // A1
                    mma16816(acc[2][nt], a[3], b1 + nt * 2);   // A3
                    mma16816(acc[3][nt], a[4], b1 + nt * 2);   // A4
                    mma16816(acc[4][nt], a[1], b2 + nt * 2);   // B1
                    mma16816(acc[5][nt], a[2], b2 + nt * 2);   // B2
                    mma16816(acc[6][nt], a[3], b2 + nt * 2);   // B3
                    mma16816(acc[7][nt], a[5], b2 + nt * 2);   // B5
                }
            }

            // epilogue: fp32 residual from buf, direct STG
            #pragma unroll
            for (int nt = 0; nt < 2; nt++) {
                const int z0 = zbase + nt * 8 + qcol;
                const float b0 = bz[nt][0], b1v = bz[nt][1];
                #pragma unroll
                for (int hh = 0; hh < 2; hh++) {
                    const int rl = qrow + hh * 8;
                    const long long row = rowb + rl;
                    if (row >= nrows) continue;
                    const float* bp = buf + rl * BSTR;
                    float* orow = out + row * (long long)ROW;
                    const int i0 = hh * 2, i1 = hh * 2 + 1;
                    float2 o;
                    o.x = bp[2*64 + z0]     + g[0] * (acc[0][nt][i0] + acc[4][nt][i0] + b0);
                    o.y = bp[2*64 + z0 + 1] + g[0] * (acc[0][nt][i1] + acc[4][nt][i1] + b1v);
                    *reinterpret_cast<float2*>(orow + 2*64 + z0) = o;
                    o.x = bp[4*64 + z0]     + g[1] * (acc[0][nt][i0] + acc[6][nt][i0] + b0);
                    o.y = bp[4*64 + z0 + 1] + g[1] * (acc[0][nt][i1] + acc[6][nt][i1] + b1v);
                    *reinterpret_cast<float2*>(orow + 4*64 + z0) = o;
                    o.x = bp[5*64 + z0]     + g[3] * (acc[1][nt][i0] + acc[6][nt][i0] + b0)
                                            + g[6] * (acc[3][nt][i0] + acc[5][nt][i0] + b0);
                    o.y = bp[5*64 + z0 + 1] + g[3] * (acc[1][nt][i1] + acc[6][nt][i1] + b1v)
                                            + g[6] * (acc[3][nt][i1] + acc[5][nt][i1] + b1v);
                    *reinterpret_cast<float2*>(orow + 5*64 + z0) = o;
                    o.x = bp[6*64 + z0]     + g[2] * (acc[0][nt][i0] + acc[7][nt][i0] + b0)
                                            + g[4] * (acc[3][nt][i0] + acc[4][nt][i0] + b0)
                                            + g[5] * (acc[2][nt][i0] + acc[5][nt][i0] + b0);
                    o.y = bp[6*64 + z0 + 1] + g[2] * (acc[0][nt][i1] + acc[7][nt][i1] + b1v)
                                            + g[4] * (acc[3][nt][i1] + acc[4][nt][i1] + b1v)
                                            + g[5] * (acc[2][nt][i1] + acc[5][nt][i1] + b1v);
                    *reinterpret_cast<float2*>(orow + 6*64 + z0) = o;
                }
            }
            BAR_ARRIVE(3 + s);                        // FREE_s
        }
    }
}

extern "C" void kernel_launch(void* const* d_in, const int* in_sizes, int n_in,
                              void* d_out, int out_size) {
    const float* x     = (const float*)d_in[0];   // colony_states [B,7,64]
    const float* W     = (const float*)d_in[1];   // [64,128]
    const float* bias  = (const float*)d_in[2];   // [64]
    const float* gates = (const float*)d_in[3];   // [7]
    float* out = (float*)d_out;

    int nrows = in_sizes[0] / ROW;
    pack_w<<<32, 256>>>(W);
    cudaFuncSetAttribute(fano_mma,
                         cudaFuncAttributeMaxDynamicSharedMemorySize, SMEM_BYTES);
    fano_mma<<<296, NTHR, SMEM_BYTES>>>(x, bias, gates, out, nrows);
}